// round 16
// baseline (speedup 1.0000x reference)
#include <cuda_runtime.h>
#include <cuda_bf16.h>
#include <cstdint>

#define DINL __device__ __forceinline__

// ---------------------------------------------------------------------------
// cseft via mma.sync bf16 hi/lo 3-pass split (base compute_103-safe).
// Factoring (no Q):
//   KT = (y@W2)^T             [1024,4096]  bf16-split
//   VT = (y@W3)^T             [1024,4096]  bf16-split
//   BmT[s][d2][hd1] = cw[h]*c * sum_i KT[hd1, s*256+i] VT[h*128+d2, s*256+i]
//   CT[s][d2][din]  = (W1 @ Bm_s)^T       [16][128][512] bf16-split
//   out[:, s*128:(s+1)*128] = x @ CT_s^T   (fp32)
// All GEMMs: D = A . B^T with A,B K-major.  10.2 GMAC (x3 passes).
// BK=32, 80 KB smem/CTA -> 2 CTAs/SM; ldmatrix + hi/lo fragment reuse.
// ---------------------------------------------------------------------------

// ---------- device scratch ----------
__device__ __nv_bfloat16 g_xhi[4096*512],   g_xlo[4096*512];
__device__ __nv_bfloat16 g_yhi[4096*512],   g_ylo[4096*512];
__device__ __nv_bfloat16 g_w1hi[512*1024],  g_w1lo[512*1024];    // non-transposed
__device__ __nv_bfloat16 g_w2thi[1024*512], g_w2tlo[1024*512];   // transposed
__device__ __nv_bfloat16 g_w3thi[1024*512], g_w3tlo[1024*512];
__device__ __nv_bfloat16 g_kthi[1024*4096], g_ktlo[1024*4096];
__device__ __nv_bfloat16 g_vthi[1024*4096], g_vtlo[1024*4096];
__device__ __nv_bfloat16 g_bmhi[16*128*1024], g_bmlo[16*128*1024];
__device__ __nv_bfloat16 g_cthi[16*128*512],  g_ctlo[16*128*512];

// ---------- helpers ----------
DINL uint32_t smem_u32(const void* p) {
    uint32_t a;
    asm("{ .reg .u64 t; cvta.to.shared.u64 t, %1; cvt.u32.u64 %0, t; }"
        : "=r"(a) : "l"(p));
    return a;
}
DINL void cp16(uint32_t s, const void* g) {
    asm volatile("cp.async.cg.shared.global [%0], [%1], 16;" :: "r"(s), "l"(g));
}
DINL void cp_commit() { asm volatile("cp.async.commit_group;" ::: "memory"); }
DINL void cp_wait1()  { asm volatile("cp.async.wait_group 1;" ::: "memory"); }
DINL void cp_wait0()  { asm volatile("cp.async.wait_group 0;" ::: "memory"); }

DINL void mma16816(float& d0, float& d1, float& d2, float& d3,
                   uint32_t a0, uint32_t a1, uint32_t a2, uint32_t a3,
                   uint32_t b0, uint32_t b1) {
    asm volatile(
        "mma.sync.aligned.m16n8k16.row.col.f32.bf16.bf16.f32 "
        "{%0,%1,%2,%3}, {%4,%5,%6,%7}, {%8,%9}, {%0,%1,%2,%3};"
        : "+f"(d0), "+f"(d1), "+f"(d2), "+f"(d3)
        : "r"(a0), "r"(a1), "r"(a2), "r"(a3), "r"(b0), "r"(b1));
}
DINL void ldsm4(uint32_t& r0, uint32_t& r1, uint32_t& r2, uint32_t& r3, uint32_t a) {
    asm volatile("ldmatrix.sync.aligned.m8n8.x4.shared.b16 {%0,%1,%2,%3}, [%4];"
                 : "=r"(r0), "=r"(r1), "=r"(r2), "=r"(r3) : "r"(a));
}
DINL uint32_t pack_hi2(float a, float b) {
    __nv_bfloat162 p = __nv_bfloat162(__float2bfloat16(a), __float2bfloat16(b));
    return *(uint32_t*)&p;
}

// ---------- conversion kernels ----------
__global__ void k_split4(const float4* __restrict__ in,
                         uint2* __restrict__ hi, uint2* __restrict__ lo, int n4) {
    for (int i = blockIdx.x * blockDim.x + threadIdx.x; i < n4;
         i += gridDim.x * blockDim.x) {
        float4 v = in[i];
        __nv_bfloat16 h0 = __float2bfloat16(v.x), h1 = __float2bfloat16(v.y);
        __nv_bfloat16 h2 = __float2bfloat16(v.z), h3 = __float2bfloat16(v.w);
        __nv_bfloat162 H0 = __nv_bfloat162(h0, h1), H1 = __nv_bfloat162(h2, h3);
        __nv_bfloat162 L0 = __nv_bfloat162(__float2bfloat16(v.x - __bfloat162float(h0)),
                                           __float2bfloat16(v.y - __bfloat162float(h1)));
        __nv_bfloat162 L1 = __nv_bfloat162(__float2bfloat16(v.z - __bfloat162float(h2)),
                                           __float2bfloat16(v.w - __bfloat162float(h3)));
        hi[i] = make_uint2(*(uint32_t*)&H0, *(uint32_t*)&H1);
        lo[i] = make_uint2(*(uint32_t*)&L0, *(uint32_t*)&L1);
    }
}
__global__ void k_splitT(const float* __restrict__ in,
                         __nv_bfloat16* __restrict__ hiT,
                         __nv_bfloat16* __restrict__ loT, int R, int C) {
    __shared__ float t[32][33];
    const int bx = blockIdx.x * 32;
    const int by = blockIdx.y * 32;
    const int tx = threadIdx.x, ty = threadIdx.y;
#pragma unroll
    for (int i = 0; i < 32; i += 8)
        t[ty + i][tx] = in[(long long)(by + ty + i) * C + bx + tx];
    __syncthreads();
#pragma unroll
    for (int i = 0; i < 32; i += 8) {
        const float v = t[tx][ty + i];
        const __nv_bfloat16 h = __float2bfloat16(v);
        const long long o = (long long)(bx + ty + i) * R + by + tx;
        hiT[o] = h;
        loT[o] = __float2bfloat16(v - __bfloat162float(h));
    }
}

// ---------------------------------------------------------------------------
// HMMA GEMM: C[128,128] tile = sum_K (Ahi Bhi^T + Ahi Blo^T + Alo Bhi^T).
// A [Mtot,Ktot], B [Ntot,Ktot], bf16 K-major. BK = 32, double-buffered cp.async,
// 80 KB smem/CTA -> 2 CTAs/SM. ldmatrix fragments loaded once per k-step,
// used by all 3 passes.
// MODE 0: fp32 C.  MODE 1: bf16-split C.  MODE 2: bf16-split C^T (smem-staged).
// ---------------------------------------------------------------------------
#define ROW_B 80           // smem row stride: 32 bf16 (64 B) + 16 B pad
#define TILE_B 10240       // 128 * 80 bytes

template <int MODE>
__global__ __launch_bounds__(256, 2) void tc_gemm(
    const __nv_bfloat16* __restrict__ Ahi, const __nv_bfloat16* __restrict__ Alo, int lda,
    const __nv_bfloat16* __restrict__ Bhi, const __nv_bfloat16* __restrict__ Blo, int ldb,
    int Ktot,
    float* __restrict__ Cf, __nv_bfloat16* __restrict__ Chi,
    __nv_bfloat16* __restrict__ Clo, int ldc,
    int zdiv,
    long long aOff1, long long aOff2, long long bOff1, long long bOff2,
    long long cOff1, long long cOff2,
    const float* __restrict__ swp, float sfac)
{
    extern __shared__ char sm[];
    const uint32_t smb = smem_u32(sm);

    const int tid = threadIdx.x;
    const int wid = tid >> 5;
    const int lane = tid & 31;
    const int g = lane >> 2;       // 0..7
    const int tig = lane & 3;      // 0..3
    const int wm = wid & 1;        // m half
    const int wn = wid >> 1;       // n quarter

    const int z = blockIdx.z;
    const int z1 = z / zdiv, z2 = z % zdiv;
    const long long offA = (long long)z1 * aOff1 + (long long)z2 * aOff2;
    const long long offB = (long long)z1 * bOff1 + (long long)z2 * bOff2;
    const long long offC = (long long)z1 * cOff1 + (long long)z2 * cOff2;
    const float scale = sfac * (swp ? swp[z1] : 1.0f);

    const int rowBase = blockIdx.y * 128;
    const int colBase = blockIdx.x * 128;

    const __nv_bfloat16* pA[2] = { Ahi + offA + (long long)rowBase * lda,
                                   Alo + offA + (long long)rowBase * lda };
    const __nv_bfloat16* pB[2] = { Bhi + offB + (long long)colBase * ldb,
                                   Blo + offB + (long long)colBase * ldb };

    // Per chunk: 4 tiles x 128 rows x 64 B = 512 cp16/tile; thread does 2/tile.
    auto load_chunk = [&](int buf, int k0) {
        const uint32_t base = smb + (uint32_t)buf * (4 * TILE_B);
#pragma unroll
        for (int i = 0; i < 2; ++i) {
            const int idx = tid + (i << 8);           // 0..511
            const int r = idx >> 2, j = idx & 3;
            const uint32_t so = (uint32_t)(r * ROW_B + j * 16);
            const long long ga = (long long)r * lda + k0 + j * 8;
            const long long gb = (long long)r * ldb + k0 + j * 8;
            cp16(base + so,              pA[0] + ga);
            cp16(base + TILE_B + so,     pA[1] + ga);
            cp16(base + 2 * TILE_B + so, pB[0] + gb);
            cp16(base + 3 * TILE_B + so, pB[1] + gb);
        }
        cp_commit();
    };

    // ldmatrix lane-dependent offsets (bytes within a tile).
    const uint32_t aLOff = (uint32_t)((lane & 15) * ROW_B + (lane >> 4) * 16);
    const uint32_t bLOff = (uint32_t)((((lane >> 4) * 8) + (lane & 7)) * ROW_B +
                                      ((lane >> 3) & 1) * 16);
    const uint32_t aWarp = (uint32_t)(wm * 64 * ROW_B);
    const uint32_t bWarp = (uint32_t)(wn * 32 * ROW_B);

    float acc[4][4][4];
#pragma unroll
    for (int i = 0; i < 4; ++i)
#pragma unroll
        for (int j = 0; j < 4; ++j)
#pragma unroll
            for (int q = 0; q < 4; ++q) acc[i][j][q] = 0.0f;

    const int nchunks = Ktot >> 5;   // BK = 32
    load_chunk(0, 0);

    for (int c = 0; c < nchunks; ++c) {
        if (c + 1 < nchunks) {
            load_chunk((c + 1) & 1, (c + 1) << 5);
            cp_wait1();
        } else {
            cp_wait0();
        }
        __syncthreads();

        const uint32_t bufb = smb + (uint32_t)(c & 1) * (4 * TILE_B);
        const uint32_t sAH = bufb + aWarp + aLOff;
        const uint32_t sAL = sAH + TILE_B;
        const uint32_t sBH = bufb + 2 * TILE_B + bWarp + bLOff;
        const uint32_t sBL = sBH + TILE_B;

#pragma unroll
        for (int ks = 0; ks < 2; ++ks) {
            const uint32_t kb = (uint32_t)(ks * 32);
            uint32_t aH[4][4], aL[4][4], bH[4][2], bL[4][2];
#pragma unroll
            for (int mi = 0; mi < 4; ++mi) {
                ldsm4(aH[mi][0], aH[mi][1], aH[mi][2], aH[mi][3],
                      sAH + (uint32_t)(mi * 16 * ROW_B) + kb);
                ldsm4(aL[mi][0], aL[mi][1], aL[mi][2], aL[mi][3],
                      sAL + (uint32_t)(mi * 16 * ROW_B) + kb);
            }
#pragma unroll
            for (int nj = 0; nj < 2; ++nj) {
                ldsm4(bH[2*nj][0], bH[2*nj][1], bH[2*nj+1][0], bH[2*nj+1][1],
                      sBH + (uint32_t)(nj * 16 * ROW_B) + kb);
                ldsm4(bL[2*nj][0], bL[2*nj][1], bL[2*nj+1][0], bL[2*nj+1][1],
                      sBL + (uint32_t)(nj * 16 * ROW_B) + kb);
            }
            // pass 0: Ahi x Bhi
#pragma unroll
            for (int mi = 0; mi < 4; ++mi)
#pragma unroll
                for (int ni = 0; ni < 4; ++ni)
                    mma16816(acc[mi][ni][0], acc[mi][ni][1], acc[mi][ni][2], acc[mi][ni][3],
                             aH[mi][0], aH[mi][1], aH[mi][2], aH[mi][3],
                             bH[ni][0], bH[ni][1]);
            // pass 1: Ahi x Blo
#pragma unroll
            for (int mi = 0; mi < 4; ++mi)
#pragma unroll
                for (int ni = 0; ni < 4; ++ni)
                    mma16816(acc[mi][ni][0], acc[mi][ni][1], acc[mi][ni][2], acc[mi][ni][3],
                             aH[mi][0], aH[mi][1], aH[mi][2], aH[mi][3],
                             bL[ni][0], bL[ni][1]);
            // pass 2: Alo x Bhi
#pragma unroll
            for (int mi = 0; mi < 4; ++mi)
#pragma unroll
                for (int ni = 0; ni < 4; ++ni)
                    mma16816(acc[mi][ni][0], acc[mi][ni][1], acc[mi][ni][2], acc[mi][ni][3],
                             aL[mi][0], aL[mi][1], aL[mi][2], aL[mi][3],
                             bH[ni][0], bH[ni][1]);
        }
        __syncthreads();
    }

    // ---- epilogue ----
    if (MODE == 2) {
        // Stage C^T into smem fp32 [128 n][132 m], then coalesced split-store.
        float* T = (float*)sm;   // 128*132*4 = 67584 <= 81920
#pragma unroll
        for (int mi = 0; mi < 4; ++mi) {
            const int rl = wm * 64 + mi * 16 + g;
#pragma unroll
            for (int ni = 0; ni < 4; ++ni) {
                const int cl = wn * 32 + ni * 8 + tig * 2;
                T[cl * 132 + rl]           = acc[mi][ni][0] * scale;
                T[(cl + 1) * 132 + rl]     = acc[mi][ni][1] * scale;
                T[cl * 132 + rl + 8]       = acc[mi][ni][2] * scale;
                T[(cl + 1) * 132 + rl + 8] = acc[mi][ni][3] * scale;
            }
        }
        __syncthreads();
        const int n = tid >> 1;
        const int mb = (tid & 1) * 64;
        const float* Tr = T + n * 132 + mb;
        __nv_bfloat16* Hp = Chi + offC + (long long)(colBase + n) * ldc + rowBase + mb;
        __nv_bfloat16* Lp = Clo + offC + (long long)(colBase + n) * ldc + rowBase + mb;
#pragma unroll
        for (int gp = 0; gp < 8; ++gp) {
            float v[8];
#pragma unroll
            for (int j = 0; j < 8; ++j) v[j] = Tr[gp * 8 + j];
            uint32_t H[4], L[4];
#pragma unroll
            for (int j = 0; j < 4; ++j) {
                const float a0 = v[2 * j], a1 = v[2 * j + 1];
                H[j] = pack_hi2(a0, a1);
                const __nv_bfloat162* hp = (const __nv_bfloat162*)&H[j];
                L[j] = pack_hi2(a0 - __bfloat162float(hp->x),
                                a1 - __bfloat162float(hp->y));
            }
            *(uint4*)(Hp + gp * 8) = *(uint4*)H;
            *(uint4*)(Lp + gp * 8) = *(uint4*)L;
        }
        return;
    }

#pragma unroll
    for (int mi = 0; mi < 4; ++mi) {
        const long long r0 = rowBase + wm * 64 + mi * 16 + g;
        const long long r1 = r0 + 8;
#pragma unroll
        for (int ni = 0; ni < 4; ++ni) {
            const long long col = colBase + wn * 32 + ni * 8 + tig * 2;
            const float v00 = acc[mi][ni][0] * scale;
            const float v01 = acc[mi][ni][1] * scale;
            const float v10 = acc[mi][ni][2] * scale;
            const float v11 = acc[mi][ni][3] * scale;

            if (MODE == 0) {
                *(float2*)(Cf + offC + r0 * ldc + col) = make_float2(v00, v01);
                *(float2*)(Cf + offC + r1 * ldc + col) = make_float2(v10, v11);
            } else {   // MODE 1
                __nv_bfloat16 h00 = __float2bfloat16(v00);
                __nv_bfloat16 h01 = __float2bfloat16(v01);
                __nv_bfloat16 h10 = __float2bfloat16(v10);
                __nv_bfloat16 h11 = __float2bfloat16(v11);
                *(__nv_bfloat162*)(Chi + offC + r0 * ldc + col) = __nv_bfloat162(h00, h01);
                *(__nv_bfloat162*)(Chi + offC + r1 * ldc + col) = __nv_bfloat162(h10, h11);
                *(__nv_bfloat162*)(Clo + offC + r0 * ldc + col) =
                    __nv_bfloat162(__float2bfloat16(v00 - __bfloat162float(h00)),
                                   __float2bfloat16(v01 - __bfloat162float(h01)));
                *(__nv_bfloat162*)(Clo + offC + r1 * ldc + col) =
                    __nv_bfloat162(__float2bfloat16(v10 - __bfloat162float(h10)),
                                   __float2bfloat16(v11 - __bfloat162float(h11)));
            }
        }
    }
}

// ---------------------------------------------------------------------------
extern "C" void kernel_launch(void* const* d_in, const int* in_sizes, int n_in,
                              void* d_out, int out_size)
{
    const float* x  = (const float*)d_in[0];   // [4096, 512]
    const float* y  = (const float*)d_in[1];   // [4096, 512]
    const float* W1 = (const float*)d_in[2];   // [512, 1024]
    const float* W2 = (const float*)d_in[3];   // [512, 1024]
    const float* W3 = (const float*)d_in[4];   // [512, 1024]
    const float* cw = (const float*)d_in[5];   // [8]
    float* out = (float*)d_out;                // [4096, 2048]

    __nv_bfloat16 *xhi, *xlo, *yhi, *ylo;
    __nv_bfloat16 *w1hi, *w1lo, *w2thi, *w2tlo, *w3thi, *w3tlo;
    __nv_bfloat16 *kthi, *ktlo, *vthi, *vtlo, *bmhi, *bmlo, *cthi, *ctlo;
    cudaGetSymbolAddress((void**)&xhi, g_xhi);     cudaGetSymbolAddress((void**)&xlo, g_xlo);
    cudaGetSymbolAddress((void**)&yhi, g_yhi);     cudaGetSymbolAddress((void**)&ylo, g_ylo);
    cudaGetSymbolAddress((void**)&w1hi, g_w1hi);   cudaGetSymbolAddress((void**)&w1lo, g_w1lo);
    cudaGetSymbolAddress((void**)&w2thi, g_w2thi); cudaGetSymbolAddress((void**)&w2tlo, g_w2tlo);
    cudaGetSymbolAddress((void**)&w3thi, g_w3thi); cudaGetSymbolAddress((void**)&w3tlo, g_w3tlo);
    cudaGetSymbolAddress((void**)&kthi, g_kthi);   cudaGetSymbolAddress((void**)&ktlo, g_ktlo);
    cudaGetSymbolAddress((void**)&vthi, g_vthi);   cudaGetSymbolAddress((void**)&vtlo, g_vtlo);
    cudaGetSymbolAddress((void**)&bmhi, g_bmhi);   cudaGetSymbolAddress((void**)&bmlo, g_bmlo);
    cudaGetSymbolAddress((void**)&cthi, g_cthi);   cudaGetSymbolAddress((void**)&ctlo, g_ctlo);

    const int SMEM_BYTES = 2 * 4 * TILE_B;   // 81920 (>= 128*132*4 staging)
    cudaFuncSetAttribute(tc_gemm<0>, cudaFuncAttributeMaxDynamicSharedMemorySize, SMEM_BYTES);
    cudaFuncSetAttribute(tc_gemm<1>, cudaFuncAttributeMaxDynamicSharedMemorySize, SMEM_BYTES);
    cudaFuncSetAttribute(tc_gemm<2>, cudaFuncAttributeMaxDynamicSharedMemorySize, SMEM_BYTES);

    dim3 t(256);

    // --- conversions ---
    k_split4<<<1024, 256>>>((const float4*)x, (uint2*)xhi, (uint2*)xlo, 4096 * 512 / 4);
    k_split4<<<1024, 256>>>((const float4*)y, (uint2*)yhi, (uint2*)ylo, 4096 * 512 / 4);
    k_split4<<<512, 256>>>((const float4*)W1, (uint2*)w1hi, (uint2*)w1lo, 512 * 1024 / 4);
    k_splitT<<<dim3(32, 16), dim3(32, 8)>>>(W2, w2thi, w2tlo, 512, 1024);
    k_splitT<<<dim3(32, 16), dim3(32, 8)>>>(W3, w3thi, w3tlo, 512, 1024);

    // G2: KT = (y@W2)^T -> bf16 split [1024,4096]
    tc_gemm<2><<<dim3(8, 32, 1), t, SMEM_BYTES>>>(
        yhi, ylo, 512, w2thi, w2tlo, 512, 512,
        nullptr, kthi, ktlo, 4096,
        1, 0, 0, 0, 0, 0, 0, nullptr, 1.0f);

    // G3: VT = (y@W3)^T -> bf16 split [1024,4096]
    tc_gemm<2><<<dim3(8, 32, 1), t, SMEM_BYTES>>>(
        yhi, ylo, 512, w3thi, w3tlo, 512, 512,
        nullptr, vthi, vtlo, 4096,
        1, 0, 0, 0, 0, 0, 0, nullptr, 1.0f);

    // G4: per z = h*16+s: D[d1,d2] = KT[h*128+d1, s*256+:256] . VT[h*128+d2, ...]^T
    //     scaled by cw[h]*inv_sqrt/256, stored transposed: BmT[s][d2][h*128+d1]
    tc_gemm<2><<<dim3(1, 1, 128), t, SMEM_BYTES>>>(
        kthi, ktlo, 4096, vthi, vtlo, 4096, 256,
        nullptr, bmhi, bmlo, 1024,
        16,
        128LL * 4096, 256LL,        // A: +h*128 rows, +s*256 k-offset
        128LL * 4096, 256LL,        // B: same
        128LL, 128LL * 1024,        // C: +h*128 col-offset, +s slab
        cw, 0.08838834764831845f / 256.0f);

    // GC: CT_s = (W1 @ Bm_s)^T -> bf16 split [16][128][512]
    tc_gemm<2><<<dim3(1, 4, 16), t, SMEM_BYTES>>>(
        w1hi, w1lo, 1024, bmhi, bmlo, 1024, 1024,
        nullptr, cthi, ctlo, 512,
        16,
        0, 0,                        // A: W1 shared
        0, 128LL * 1024,             // B: +s slab
        0, 128LL * 512,              // C: +s slab
        nullptr, 1.0f);

    // GD: out[:, s*128:(s+1)*128] = x @ CT_s^T  (fp32)
    tc_gemm<0><<<dim3(1, 32, 16), t, SMEM_BYTES>>>(
        xhi, xlo, 512, cthi, ctlo, 512, 512,
        out, nullptr, nullptr, 2048,
        16,
        0, 0,                        // A: x shared
        0, 128LL * 512,              // B: +s slab
        0, 128LL,                    // C: +s*128 col offset
        nullptr, 1.0f);
}

// round 17
// speedup vs baseline: 1.1989x; 1.1989x over previous
#include <cuda_runtime.h>
#include <cuda_bf16.h>
#include <cuda_fp16.h>
#include <cstdint>

#define DINL __device__ __forceinline__

// ---------------------------------------------------------------------------
// cseft via mma.sync hi/lo split (base compute_103-safe).
//   G23: KT=(y@W2)^T, VT=(y@W3)^T merged (bf16 3-pass)  [2][1024,4096]
//   G4 : BmT[s][d2][hd1] = cw[h]*c*sum_i KT[hd1,s*256+i] VT[h*128+d2,s*256+i]
//   GC : split-K x4 fp32 partials of C_s = W1 @ Bm_s    (bf16 3-pass)
//   RED: sum partials, transpose, fp16-split -> CT[16][128][512]
//   GD : out[:,s*128:+128] = x @ CT_s^T  (fp16 2-pass: x single, CT hi/lo)
// ---------------------------------------------------------------------------

// ---------- device scratch ----------
__device__ __nv_bfloat16 g_yhi[4096*512],   g_ylo[4096*512];
__device__ __nv_bfloat16 g_w1hi[512*1024],  g_w1lo[512*1024];
__device__ __nv_bfloat16 g_w23thi[2*1024*512], g_w23tlo[2*1024*512];  // W2T|W3T
__device__ __nv_bfloat16 g_kvthi[2LL*1024*4096], g_kvtlo[2LL*1024*4096]; // KT|VT
__device__ __nv_bfloat16 g_bmhi[16*128*1024], g_bmlo[16*128*1024];
__device__ float  g_gcp[4LL*16*512*128];        // GC split-K partials
__device__ __half g_cth16[16*128*512], g_ctl16[16*128*512];
__device__ __half g_xf16[4096*512];

// ---------- helpers ----------
DINL uint32_t smem_u32(const void* p) {
    uint32_t a;
    asm("{ .reg .u64 t; cvta.to.shared.u64 t, %1; cvt.u32.u64 %0, t; }"
        : "=r"(a) : "l"(p));
    return a;
}
DINL void cp16(uint32_t s, const void* g) {
    asm volatile("cp.async.cg.shared.global [%0], [%1], 16;" :: "r"(s), "l"(g));
}
DINL void cp_commit() { asm volatile("cp.async.commit_group;" ::: "memory"); }
DINL void cp_wait1()  { asm volatile("cp.async.wait_group 1;" ::: "memory"); }
DINL void cp_wait0()  { asm volatile("cp.async.wait_group 0;" ::: "memory"); }

DINL void mma_bf16(float& d0, float& d1, float& d2, float& d3,
                   uint32_t a0, uint32_t a1, uint32_t a2, uint32_t a3,
                   uint32_t b0, uint32_t b1) {
    asm volatile(
        "mma.sync.aligned.m16n8k16.row.col.f32.bf16.bf16.f32 "
        "{%0,%1,%2,%3}, {%4,%5,%6,%7}, {%8,%9}, {%0,%1,%2,%3};"
        : "+f"(d0), "+f"(d1), "+f"(d2), "+f"(d3)
        : "r"(a0), "r"(a1), "r"(a2), "r"(a3), "r"(b0), "r"(b1));
}
DINL void mma_fp16(float& d0, float& d1, float& d2, float& d3,
                   uint32_t a0, uint32_t a1, uint32_t a2, uint32_t a3,
                   uint32_t b0, uint32_t b1) {
    asm volatile(
        "mma.sync.aligned.m16n8k16.row.col.f32.f16.f16.f32 "
        "{%0,%1,%2,%3}, {%4,%5,%6,%7}, {%8,%9}, {%0,%1,%2,%3};"
        : "+f"(d0), "+f"(d1), "+f"(d2), "+f"(d3)
        : "r"(a0), "r"(a1), "r"(a2), "r"(a3), "r"(b0), "r"(b1));
}
DINL void ldsm4(uint32_t& r0, uint32_t& r1, uint32_t& r2, uint32_t& r3, uint32_t a) {
    asm volatile("ldmatrix.sync.aligned.m8n8.x4.shared.b16 {%0,%1,%2,%3}, [%4];"
                 : "=r"(r0), "=r"(r1), "=r"(r2), "=r"(r3) : "r"(a));
}
DINL uint32_t pack_hi2(float a, float b) {
    __nv_bfloat162 p = __nv_bfloat162(__float2bfloat16(a), __float2bfloat16(b));
    return *(uint32_t*)&p;
}

// ---------- conversion kernels ----------
__global__ void k_split4(const float4* __restrict__ in,
                         uint2* __restrict__ hi, uint2* __restrict__ lo, int n4) {
    for (int i = blockIdx.x * blockDim.x + threadIdx.x; i < n4;
         i += gridDim.x * blockDim.x) {
        float4 v = in[i];
        __nv_bfloat16 h0 = __float2bfloat16(v.x), h1 = __float2bfloat16(v.y);
        __nv_bfloat16 h2 = __float2bfloat16(v.z), h3 = __float2bfloat16(v.w);
        __nv_bfloat162 H0 = __nv_bfloat162(h0, h1), H1 = __nv_bfloat162(h2, h3);
        __nv_bfloat162 L0 = __nv_bfloat162(__float2bfloat16(v.x - __bfloat162float(h0)),
                                           __float2bfloat16(v.y - __bfloat162float(h1)));
        __nv_bfloat162 L1 = __nv_bfloat162(__float2bfloat16(v.z - __bfloat162float(h2)),
                                           __float2bfloat16(v.w - __bfloat162float(h3)));
        hi[i] = make_uint2(*(uint32_t*)&H0, *(uint32_t*)&H1);
        lo[i] = make_uint2(*(uint32_t*)&L0, *(uint32_t*)&L1);
    }
}
__global__ void k_tofp16(const float4* __restrict__ in, uint2* __restrict__ o, int n4) {
    for (int i = blockIdx.x * blockDim.x + threadIdx.x; i < n4;
         i += gridDim.x * blockDim.x) {
        float4 v = in[i];
        __half2 a = __floats2half2_rn(v.x, v.y);
        __half2 b = __floats2half2_rn(v.z, v.w);
        o[i] = make_uint2(*(uint32_t*)&a, *(uint32_t*)&b);
    }
}
__global__ void k_splitT(const float* __restrict__ in,
                         __nv_bfloat16* __restrict__ hiT,
                         __nv_bfloat16* __restrict__ loT, int R, int C) {
    __shared__ float t[32][33];
    const int bx = blockIdx.x * 32;
    const int by = blockIdx.y * 32;
    const int tx = threadIdx.x, ty = threadIdx.y;
#pragma unroll
    for (int i = 0; i < 32; i += 8)
        t[ty + i][tx] = in[(long long)(by + ty + i) * C + bx + tx];
    __syncthreads();
#pragma unroll
    for (int i = 0; i < 32; i += 8) {
        const float v = t[tx][ty + i];
        const __nv_bfloat16 h = __float2bfloat16(v);
        const long long o = (long long)(bx + ty + i) * R + by + tx;
        hiT[o] = h;
        loT[o] = __float2bfloat16(v - __bfloat162float(h));
    }
}
// Sum 4 split-K partials P[c][s][din][d2], transpose to CT[s][d2][din], fp16 split.
__global__ void k_redT(const float* __restrict__ P,
                       __half* __restrict__ hi, __half* __restrict__ lo) {
    __shared__ float t[32][33];
    const int s = blockIdx.z;
    const int bx = blockIdx.x * 32;   // din base
    const int by = blockIdx.y * 32;   // d2 base
    const int tx = threadIdx.x, ty = threadIdx.y;
    const long long CH = 16LL * 512 * 128;
#pragma unroll
    for (int i = 0; i < 32; i += 8) {
        const long long off = ((long long)s * 512 + bx + ty + i) * 128 + by + tx;
        t[ty + i][tx] = P[off] + P[CH + off] + P[2 * CH + off] + P[3 * CH + off];
    }
    __syncthreads();
#pragma unroll
    for (int i = 0; i < 32; i += 8) {
        const float v = t[tx][ty + i];
        const __half h = __float2half(v);
        const long long o = ((long long)s * 128 + by + ty + i) * 512 + bx + tx;
        hi[o] = h;
        lo[o] = __float2half(v - __half2float(h));
    }
}

// ---------------------------------------------------------------------------
// HMMA GEMM, 128x128 CTA tile, BK=64, double-buffered cp.async, ldmatrix.
// NPASS=3: D = AhiBhi^T + AhiBlo^T + AloBhi^T.  NPASS=2: D = AhiBhi^T + AhiBlo^T.
// FP16: f16 mma (else bf16).  MODE 0: fp32 C.  MODE 2: bf16-split C^T (staged).
// ---------------------------------------------------------------------------
#define TILE_B 18432       // 128 * 144 bytes

template <int MODE, int NPASS, int FP16>
__global__ __launch_bounds__(256) void tc_gemm(
    const __nv_bfloat16* __restrict__ Ahi, const __nv_bfloat16* __restrict__ Alo, int lda,
    const __nv_bfloat16* __restrict__ Bhi, const __nv_bfloat16* __restrict__ Blo, int ldb,
    int Ktot,
    float* __restrict__ Cf, __nv_bfloat16* __restrict__ Chi,
    __nv_bfloat16* __restrict__ Clo, int ldc,
    int zdiv,
    long long aOff1, long long aOff2, long long bOff1, long long bOff2,
    long long cOff1, long long cOff2,
    const float* __restrict__ swp, float sfac)
{
    extern __shared__ char sm[];
    const uint32_t smb = smem_u32(sm);

    const int tid = threadIdx.x;
    const int wid = tid >> 5;
    const int lane = tid & 31;
    const int g = lane >> 2;
    const int tig = lane & 3;
    const int wm = wid & 1;
    const int wn = wid >> 1;

    const int z = blockIdx.z;
    const int z1 = z / zdiv, z2 = z % zdiv;
    const long long offA = (long long)z1 * aOff1 + (long long)z2 * aOff2;
    const long long offB = (long long)z1 * bOff1 + (long long)z2 * bOff2;
    const long long offC = (long long)z1 * cOff1 + (long long)z2 * cOff2;
    const float scale = sfac * (swp ? swp[z1] : 1.0f);

    const int rowBase = blockIdx.y * 128;
    const int colBase = blockIdx.x * 128;

    const __nv_bfloat16* pA0 = Ahi + offA + (long long)rowBase * lda;
    const __nv_bfloat16* pA1 = Alo + offA + (long long)rowBase * lda;
    const __nv_bfloat16* pB0 = Bhi + offB + (long long)colBase * ldb;
    const __nv_bfloat16* pB1 = Blo + offB + (long long)colBase * ldb;

    auto load_chunk = [&](int buf, int k0) {
        const uint32_t base = smb + (uint32_t)buf * (4 * TILE_B);
#pragma unroll
        for (int i = 0; i < 4; ++i) {
            const int idx = tid + (i << 8);
            const int r = idx >> 3, j = idx & 7;
            const uint32_t so = (uint32_t)(r * 144 + j * 16);
            const long long ga = (long long)r * lda + k0 + j * 8;
            const long long gb = (long long)r * ldb + k0 + j * 8;
            cp16(base + so,              pA0 + ga);
            if (NPASS == 3) cp16(base + TILE_B + so, pA1 + ga);
            cp16(base + 2 * TILE_B + so, pB0 + gb);
            cp16(base + 3 * TILE_B + so, pB1 + gb);
        }
        cp_commit();
    };

    const uint32_t aLOff = (uint32_t)((lane & 15) * 144 + (lane >> 4) * 16);
    const uint32_t bLOff = (uint32_t)((((lane >> 4) * 8) + (lane & 7)) * 144 +
                                      ((lane >> 3) & 1) * 16);
    const uint32_t aWarp = (uint32_t)(wm * 64 * 144);
    const uint32_t bWarp = (uint32_t)(wn * 32 * 144);

    float acc[4][4][4];
#pragma unroll
    for (int i = 0; i < 4; ++i)
#pragma unroll
        for (int j = 0; j < 4; ++j)
#pragma unroll
            for (int q = 0; q < 4; ++q) acc[i][j][q] = 0.0f;

    const int nchunks = Ktot >> 6;
    load_chunk(0, 0);

    for (int c = 0; c < nchunks; ++c) {
        if (c + 1 < nchunks) {
            load_chunk((c + 1) & 1, (c + 1) << 6);
            cp_wait1();
        } else {
            cp_wait0();
        }
        __syncthreads();

        const uint32_t bufb = smb + (uint32_t)(c & 1) * (4 * TILE_B);
        const uint32_t sAH = bufb + aWarp + aLOff;
        const uint32_t sAL = sAH + TILE_B;
        const uint32_t sBH = bufb + 2 * TILE_B + bWarp + bLOff;
        const uint32_t sBL = sBH + TILE_B;

#pragma unroll
        for (int ks = 0; ks < 4; ++ks) {
            const uint32_t kb = (uint32_t)(ks * 32);
            uint32_t aH[4][4], aL[4][4], bH[4][2], bL[4][2];
#pragma unroll
            for (int mi = 0; mi < 4; ++mi) {
                ldsm4(aH[mi][0], aH[mi][1], aH[mi][2], aH[mi][3],
                      sAH + (uint32_t)(mi * 16 * 144) + kb);
                if (NPASS == 3)
                    ldsm4(aL[mi][0], aL[mi][1], aL[mi][2], aL[mi][3],
                          sAL + (uint32_t)(mi * 16 * 144) + kb);
            }
#pragma unroll
            for (int nj = 0; nj < 2; ++nj) {
                ldsm4(bH[2*nj][0], bH[2*nj][1], bH[2*nj+1][0], bH[2*nj+1][1],
                      sBH + (uint32_t)(nj * 16 * 144) + kb);
                ldsm4(bL[2*nj][0], bL[2*nj][1], bL[2*nj+1][0], bL[2*nj+1][1],
                      sBL + (uint32_t)(nj * 16 * 144) + kb);
            }
#define MMA_GO(AA, BB)                                                         \
            for (int mi = 0; mi < 4; ++mi)                                     \
                for (int ni = 0; ni < 4; ++ni) {                               \
                    if (FP16) mma_fp16(acc[mi][ni][0], acc[mi][ni][1],         \
                                       acc[mi][ni][2], acc[mi][ni][3],         \
                                       AA[mi][0], AA[mi][1], AA[mi][2], AA[mi][3], \
                                       BB[ni][0], BB[ni][1]);                  \
                    else      mma_bf16(acc[mi][ni][0], acc[mi][ni][1],         \
                                       acc[mi][ni][2], acc[mi][ni][3],         \
                                       AA[mi][0], AA[mi][1], AA[mi][2], AA[mi][3], \
                                       BB[ni][0], BB[ni][1]);                  \
                }
            MMA_GO(aH, bH)
            MMA_GO(aH, bL)
            if (NPASS == 3) { MMA_GO(aL, bH) }
#undef MMA_GO
        }
        __syncthreads();
    }

    // ---- epilogue ----
    if (MODE == 2) {
        float* T = (float*)sm;
#pragma unroll
        for (int mi = 0; mi < 4; ++mi) {
            const int rl = wm * 64 + mi * 16 + g;
#pragma unroll
            for (int ni = 0; ni < 4; ++ni) {
                const int cl = wn * 32 + ni * 8 + tig * 2;
                T[cl * 132 + rl]           = acc[mi][ni][0] * scale;
                T[(cl + 1) * 132 + rl]     = acc[mi][ni][1] * scale;
                T[cl * 132 + rl + 8]       = acc[mi][ni][2] * scale;
                T[(cl + 1) * 132 + rl + 8] = acc[mi][ni][3] * scale;
            }
        }
        __syncthreads();
        const int n = tid >> 1;
        const int mb = (tid & 1) * 64;
        const float* Tr = T + n * 132 + mb;
        __nv_bfloat16* Hp = Chi + offC + (long long)(colBase + n) * ldc + rowBase + mb;
        __nv_bfloat16* Lp = Clo + offC + (long long)(colBase + n) * ldc + rowBase + mb;
#pragma unroll
        for (int gp = 0; gp < 8; ++gp) {
            float v[8];
#pragma unroll
            for (int j = 0; j < 8; ++j) v[j] = Tr[gp * 8 + j];
            uint32_t H[4], L[4];
#pragma unroll
            for (int j = 0; j < 4; ++j) {
                const float a0 = v[2 * j], a1 = v[2 * j + 1];
                H[j] = pack_hi2(a0, a1);
                const __nv_bfloat162* hp = (const __nv_bfloat162*)&H[j];
                L[j] = pack_hi2(a0 - __bfloat162float(hp->x),
                                a1 - __bfloat162float(hp->y));
            }
            *(uint4*)(Hp + gp * 8) = *(uint4*)H;
            *(uint4*)(Lp + gp * 8) = *(uint4*)L;
        }
        return;
    }

#pragma unroll
    for (int mi = 0; mi < 4; ++mi) {
        const long long r0 = rowBase + wm * 64 + mi * 16 + g;
        const long long r1 = r0 + 8;
#pragma unroll
        for (int ni = 0; ni < 4; ++ni) {
            const long long col = colBase + wn * 32 + ni * 8 + tig * 2;
            *(float2*)(Cf + offC + r0 * ldc + col) =
                make_float2(acc[mi][ni][0] * scale, acc[mi][ni][1] * scale);
            *(float2*)(Cf + offC + r1 * ldc + col) =
                make_float2(acc[mi][ni][2] * scale, acc[mi][ni][3] * scale);
        }
    }
}

// ---------------------------------------------------------------------------
extern "C" void kernel_launch(void* const* d_in, const int* in_sizes, int n_in,
                              void* d_out, int out_size)
{
    const float* x  = (const float*)d_in[0];   // [4096, 512]
    const float* y  = (const float*)d_in[1];   // [4096, 512]
    const float* W1 = (const float*)d_in[2];   // [512, 1024]
    const float* W2 = (const float*)d_in[3];   // [512, 1024]
    const float* W3 = (const float*)d_in[4];   // [512, 1024]
    const float* cw = (const float*)d_in[5];   // [8]
    float* out = (float*)d_out;                // [4096, 2048]

    __nv_bfloat16 *yhi, *ylo, *w1hi, *w1lo, *w23thi, *w23tlo;
    __nv_bfloat16 *kvthi, *kvtlo, *bmhi, *bmlo;
    float* gcp; __half *cth, *ctl, *xf;
    cudaGetSymbolAddress((void**)&yhi, g_yhi);       cudaGetSymbolAddress((void**)&ylo, g_ylo);
    cudaGetSymbolAddress((void**)&w1hi, g_w1hi);     cudaGetSymbolAddress((void**)&w1lo, g_w1lo);
    cudaGetSymbolAddress((void**)&w23thi, g_w23thi); cudaGetSymbolAddress((void**)&w23tlo, g_w23tlo);
    cudaGetSymbolAddress((void**)&kvthi, g_kvthi);   cudaGetSymbolAddress((void**)&kvtlo, g_kvtlo);
    cudaGetSymbolAddress((void**)&bmhi, g_bmhi);     cudaGetSymbolAddress((void**)&bmlo, g_bmlo);
    cudaGetSymbolAddress((void**)&gcp, g_gcp);
    cudaGetSymbolAddress((void**)&cth, g_cth16);     cudaGetSymbolAddress((void**)&ctl, g_ctl16);
    cudaGetSymbolAddress((void**)&xf, g_xf16);

    const int SMEM_BYTES = 2 * 4 * TILE_B;   // 147456
    cudaFuncSetAttribute(tc_gemm<2,3,0>, cudaFuncAttributeMaxDynamicSharedMemorySize, SMEM_BYTES);
    cudaFuncSetAttribute(tc_gemm<0,3,0>, cudaFuncAttributeMaxDynamicSharedMemorySize, SMEM_BYTES);
    cudaFuncSetAttribute(tc_gemm<0,2,1>, cudaFuncAttributeMaxDynamicSharedMemorySize, SMEM_BYTES);

    dim3 t(256);
    const long long KVSLAB = 1024LL * 4096;

    // --- conversions ---
    k_split4<<<1024, 256>>>((const float4*)y, (uint2*)yhi, (uint2*)ylo, 4096 * 512 / 4);
    k_tofp16<<<512, 256>>>((const float4*)x, (uint2*)xf, 4096 * 512 / 4);
    k_split4<<<512, 256>>>((const float4*)W1, (uint2*)w1hi, (uint2*)w1lo, 512 * 1024 / 4);
    k_splitT<<<dim3(32, 16), dim3(32, 8)>>>(W2, w23thi, w23tlo, 512, 1024);
    k_splitT<<<dim3(32, 16), dim3(32, 8)>>>(W3, w23thi + 512 * 1024, w23tlo + 512 * 1024, 512, 1024);

    // G23: KT|VT = (y@W2)^T | (y@W3)^T merged, bf16 3-pass -> [2][1024,4096]
    tc_gemm<2,3,0><<<dim3(8, 32, 2), t, SMEM_BYTES>>>(
        yhi, ylo, 512, w23thi, w23tlo, 512, 512,
        nullptr, kvthi, kvtlo, 4096,
        1,
        0, 0, 512LL * 1024, 0, KVSLAB, 0,
        nullptr, 1.0f);

    // G4: BmT[s][d2][h*128+d1], z = h*16+s, scaled by cw[h]*inv_sqrt/256
    tc_gemm<2,3,0><<<dim3(1, 1, 128), t, SMEM_BYTES>>>(
        kvthi, kvtlo, 4096, kvthi + KVSLAB, kvtlo + KVSLAB, 4096, 256,
        nullptr, bmhi, bmlo, 1024,
        16,
        128LL * 4096, 256LL,
        128LL * 4096, 256LL,
        128LL, 128LL * 1024,
        cw, 0.08838834764831845f / 256.0f);

    // GC split-K x4: partial[c][s] = W1 @ Bm_s over k-chunk c (fp32), z = s*4+c
    tc_gemm<0,3,0><<<dim3(1, 4, 64), t, SMEM_BYTES>>>(
        w1hi, w1lo, 1024, bmhi, bmlo, 1024, 256,
        gcp, nullptr, nullptr, 128,
        4,
        0, 256LL,
        128LL * 1024, 256LL,
        512LL * 128, 16LL * 512 * 128,
        nullptr, 1.0f);

    // RED: sum 4 partials, transpose, fp16-split -> CT[16][128][512]
    k_redT<<<dim3(16, 4, 16), dim3(32, 8)>>>(gcp, cth, ctl);

    // GD: out[:, s*128:+128] = x @ CT_s^T, fp16 2-pass (x single, CT hi/lo)
    tc_gemm<0,2,1><<<dim3(1, 32, 16), t, SMEM_BYTES>>>(
        (const __nv_bfloat16*)xf, (const __nv_bfloat16*)xf, 512,
        (const __nv_bfloat16*)cth, (const __nv_bfloat16*)ctl, 512, 512,
        out, nullptr, nullptr, 2048,
        16,
        0, 0,
        0, 128LL * 512,
        0, 128LL,
        nullptr, 1.0f);
}